// round 1
// baseline (speedup 1.0000x reference)
#include <cuda_runtime.h>

// Problem constants (fixed by the reference): N=100000, E=3200000, FEAT=128, HID=32, EMB=16
#define NMAX 100000

// Scratch (device globals: no allocation allowed in kernel_launch)
__device__ float g_h1 [NMAX * 32];
__device__ float g_acc1[NMAX * 32];
__device__ float g_als1[NMAX];
__device__ float g_ald1[NMAX];
__device__ float g_den1[NMAX];
__device__ float g_h2 [NMAX * 16];
__device__ float g_acc2[NMAX * 16];
__device__ float g_als2[NMAX];
__device__ float g_ald2[NMAX];
__device__ float g_den2[NMAX];

__device__ __forceinline__ float leaky(float a) { return a > 0.0f ? a : 0.2f * a; }

__device__ __forceinline__ void red_add_v4(float* p, float4 v) {
    asm volatile("red.global.add.v4.f32 [%0], {%1, %2, %3, %4};"
                 :: "l"(p), "f"(v.x), "f"(v.y), "f"(v.z), "f"(v.w) : "memory");
}

// ---------------------------------------------------------------------------
// K1: h1 = x @ W1; al_s1/al_d1; init acc1/den1 with self-loop contribution
// ---------------------------------------------------------------------------
__global__ __launch_bounds__(256) void node1_kernel(
    const float* __restrict__ x, const float* __restrict__ W1,
    const float* __restrict__ asrc, const float* __restrict__ adst, int N)
{
    __shared__ float Ws[128 * 32];
    __shared__ float s_as[32], s_ad[32];
    for (int i = threadIdx.x; i < 128 * 32; i += 256) Ws[i] = W1[i];
    if (threadIdx.x < 32) { s_as[threadIdx.x] = asrc[threadIdx.x]; s_ad[threadIdx.x] = adst[threadIdx.x]; }
    __syncthreads();

    int n = blockIdx.x * 256 + threadIdx.x;
    if (n >= N) return;

    float4 acc[8];
#pragma unroll
    for (int i = 0; i < 8; i++) acc[i] = make_float4(0.f, 0.f, 0.f, 0.f);

    const float4* xr = reinterpret_cast<const float4*>(x + (size_t)n * 128);
#pragma unroll 4
    for (int k4 = 0; k4 < 32; k4++) {
        float4 xv = __ldg(&xr[k4]);
        float xk[4] = {xv.x, xv.y, xv.z, xv.w};
#pragma unroll
        for (int kk = 0; kk < 4; kk++) {
            const float4* wr = reinterpret_cast<const float4*>(&Ws[(k4 * 4 + kk) * 32]);
            float xs = xk[kk];
#pragma unroll
            for (int c4 = 0; c4 < 8; c4++) {
                float4 w = wr[c4];
                acc[c4].x += xs * w.x; acc[c4].y += xs * w.y;
                acc[c4].z += xs * w.z; acc[c4].w += xs * w.w;
            }
        }
    }

    float als = 0.f, ald = 0.f;
#pragma unroll
    for (int c4 = 0; c4 < 8; c4++) {
        float4 a  = acc[c4];
        float4 s4 = reinterpret_cast<const float4*>(s_as)[c4];
        float4 d4 = reinterpret_cast<const float4*>(s_ad)[c4];
        als += a.x * s4.x + a.y * s4.y + a.z * s4.z + a.w * s4.w;
        ald += a.x * d4.x + a.y * d4.y + a.z * d4.z + a.w * d4.w;
    }
    float w = __expf(leaky(als + ald));   // self-loop weight
    g_als1[n] = als; g_ald1[n] = ald; g_den1[n] = w;

    float4* hp = reinterpret_cast<float4*>(&g_h1 [n * 32]);
    float4* ap = reinterpret_cast<float4*>(&g_acc1[n * 32]);
#pragma unroll
    for (int c4 = 0; c4 < 8; c4++) {
        hp[c4] = acc[c4];
        ap[c4] = make_float4(w * acc[c4].x, w * acc[c4].y, w * acc[c4].z, w * acc[c4].w);
    }
}

// ---------------------------------------------------------------------------
// K2: layer-1 edge pass. 8 lanes per edge (32 channels / 4 per lane).
// ---------------------------------------------------------------------------
__global__ __launch_bounds__(256) void edge1_kernel(
    const int* __restrict__ src, const int* __restrict__ dst, int E)
{
    int t = blockIdx.x * 256 + threadIdx.x;
    int e = t >> 3;
    if (e >= E) return;
    int lane = t & 7;
    int s = __ldg(src + e);
    int d = __ldg(dst + e);
    float a = __ldg(&g_als1[s]) + __ldg(&g_ald1[d]);
    float w = __expf(leaky(a));
    if (lane == 0) atomicAdd(&g_den1[d], w);
    float4 h4 = *reinterpret_cast<const float4*>(&g_h1[s * 32 + lane * 4]);
    red_add_v4(&g_acc1[d * 32 + lane * 4],
               make_float4(w * h4.x, w * h4.y, w * h4.z, w * h4.w));
}

// ---------------------------------------------------------------------------
// K3: finalize layer1 (+relu), h2 = h' @ W2, al2, self-loop init for layer2
// ---------------------------------------------------------------------------
__global__ __launch_bounds__(256) void node2_kernel(
    const float* __restrict__ b1, const float* __restrict__ W2,
    const float* __restrict__ asrc, const float* __restrict__ adst, int N)
{
    __shared__ float Ws[32 * 16];
    __shared__ float s_b1[32], s_as[16], s_ad[16];
    for (int i = threadIdx.x; i < 32 * 16; i += 256) Ws[i] = W2[i];
    if (threadIdx.x < 32) s_b1[threadIdx.x] = b1[threadIdx.x];
    if (threadIdx.x < 16) { s_as[threadIdx.x] = asrc[threadIdx.x]; s_ad[threadIdx.x] = adst[threadIdx.x]; }
    __syncthreads();

    int n = blockIdx.x * 256 + threadIdx.x;
    if (n >= N) return;

    float inv = 1.0f / (g_den1[n] + 1e-16f);
    float hv[32];
    const float4* ap = reinterpret_cast<const float4*>(&g_acc1[n * 32]);
#pragma unroll
    for (int c4 = 0; c4 < 8; c4++) {
        float4 a = ap[c4];
        hv[c4 * 4 + 0] = fmaxf(a.x * inv + s_b1[c4 * 4 + 0], 0.f);
        hv[c4 * 4 + 1] = fmaxf(a.y * inv + s_b1[c4 * 4 + 1], 0.f);
        hv[c4 * 4 + 2] = fmaxf(a.z * inv + s_b1[c4 * 4 + 2], 0.f);
        hv[c4 * 4 + 3] = fmaxf(a.w * inv + s_b1[c4 * 4 + 3], 0.f);
    }

    float4 h2[4];
#pragma unroll
    for (int i = 0; i < 4; i++) h2[i] = make_float4(0.f, 0.f, 0.f, 0.f);
#pragma unroll
    for (int c = 0; c < 32; c++) {
        float xs = hv[c];
        const float4* wr = reinterpret_cast<const float4*>(&Ws[c * 16]);
#pragma unroll
        for (int c4 = 0; c4 < 4; c4++) {
            float4 w = wr[c4];
            h2[c4].x += xs * w.x; h2[c4].y += xs * w.y;
            h2[c4].z += xs * w.z; h2[c4].w += xs * w.w;
        }
    }

    float als = 0.f, ald = 0.f;
#pragma unroll
    for (int c4 = 0; c4 < 4; c4++) {
        float4 a  = h2[c4];
        float4 s4 = reinterpret_cast<const float4*>(s_as)[c4];
        float4 d4 = reinterpret_cast<const float4*>(s_ad)[c4];
        als += a.x * s4.x + a.y * s4.y + a.z * s4.z + a.w * s4.w;
        ald += a.x * d4.x + a.y * d4.y + a.z * d4.z + a.w * d4.w;
    }
    float w = __expf(leaky(als + ald));
    g_als2[n] = als; g_ald2[n] = ald; g_den2[n] = w;

    float4* hp = reinterpret_cast<float4*>(&g_h2 [n * 16]);
    float4* cp = reinterpret_cast<float4*>(&g_acc2[n * 16]);
#pragma unroll
    for (int c4 = 0; c4 < 4; c4++) {
        hp[c4] = h2[c4];
        cp[c4] = make_float4(w * h2[c4].x, w * h2[c4].y, w * h2[c4].z, w * h2[c4].w);
    }
}

// ---------------------------------------------------------------------------
// K4: layer-2 edge pass. 4 lanes per edge (16 channels / 4 per lane).
// ---------------------------------------------------------------------------
__global__ __launch_bounds__(256) void edge2_kernel(
    const int* __restrict__ src, const int* __restrict__ dst, int E)
{
    int t = blockIdx.x * 256 + threadIdx.x;
    int e = t >> 2;
    if (e >= E) return;
    int lane = t & 3;
    int s = __ldg(src + e);
    int d = __ldg(dst + e);
    float a = __ldg(&g_als2[s]) + __ldg(&g_ald2[d]);
    float w = __expf(leaky(a));
    if (lane == 0) atomicAdd(&g_den2[d], w);
    float4 h4 = *reinterpret_cast<const float4*>(&g_h2[s * 16 + lane * 4]);
    red_add_v4(&g_acc2[d * 16 + lane * 4],
               make_float4(w * h4.x, w * h4.y, w * h4.z, w * h4.w));
}

// ---------------------------------------------------------------------------
// K5: out = acc2 / (den2 + eps) + b2
// ---------------------------------------------------------------------------
__global__ __launch_bounds__(256) void final_kernel(
    const float* __restrict__ b2, float* __restrict__ out, int N)
{
    int t = blockIdx.x * 256 + threadIdx.x;
    int n = t >> 2;
    if (n >= N) return;
    int c4 = t & 3;
    float4 a = reinterpret_cast<const float4*>(g_acc2)[n * 4 + c4];
    float inv = 1.0f / (g_den2[n] + 1e-16f);
    float4 b = __ldg(&reinterpret_cast<const float4*>(b2)[c4]);
    reinterpret_cast<float4*>(out)[n * 4 + c4] =
        make_float4(a.x * inv + b.x, a.y * inv + b.y, a.z * inv + b.z, a.w * inv + b.w);
}

extern "C" void kernel_launch(void* const* d_in, const int* in_sizes, int n_in,
                              void* d_out, int out_size)
{
    const float* x   = (const float*)d_in[0];
    const int*   ei  = (const int*)  d_in[1];
    // d_in[2] = ew, unused by GATConv (edge_dim=None)
    const float* W1  = (const float*)d_in[3];
    const float* as1 = (const float*)d_in[4];
    const float* ad1 = (const float*)d_in[5];
    const float* b1  = (const float*)d_in[6];
    const float* W2  = (const float*)d_in[7];
    const float* as2 = (const float*)d_in[8];
    const float* ad2 = (const float*)d_in[9];
    const float* b2  = (const float*)d_in[10];

    int N = in_sizes[0] / 128;
    int E = in_sizes[1] / 2;
    const int* src = ei;
    const int* dst = ei + E;

    node1_kernel<<<(N + 255) / 256, 256>>>(x, W1, as1, ad1, N);
    edge1_kernel<<<(int)(((long long)E * 8 + 255) / 256), 256>>>(src, dst, E);
    node2_kernel<<<(N + 255) / 256, 256>>>(b1, W2, as2, ad2, N);
    edge2_kernel<<<(int)(((long long)E * 4 + 255) / 256), 256>>>(src, dst, E);
    final_kernel<<<(int)(((long long)N * 4 + 255) / 256), 256>>>(b2, (float*)d_out, N);
}